// round 6
// baseline (speedup 1.0000x reference)
#include <cuda_runtime.h>

// GARCH(1,1): h[t] = (omega + alpha*r[t-1]^2) + beta*h[t-1], h[0] = var(r, ddof=1)
// out[0..n) = sqrt(h), out[n..2n) = h
//
// Register/shuffle-only, software-pipelined, occupancy-tuned. beta<1 =>
// contractive (beta^256 ~ 8e-19 < fp32 ulp): each WARP produces a 2048-output
// span with a 256-elem warm-up halo, streaming 256-elem segments (8 per lane):
//   prefetched 2x LDG.128 -> shfl boundary shift -> 7-FMA local chain ->
//   5-step Kogge-Stone scan (multipliers beta^(8*2^k)) -> carry apply ->
//   sqrt.approx -> 4x STG.128 (streaming).
// Segment carry c_next = scan end (the beta^256*c_prev term is dropped as
// negligible), so consecutive segments have no serial dependency chain.
// True h[t] = h_hat[t] + beta^t*h0 (linearity); patched by last block (ticket).

#define TPB    256
#define WARPS  (TPB/32)
#define EPL    8
#define SEG    (32*EPL)          // 256
#define HSEG   1
#define OSEG   8
#define TSEG   (HSEG + OSEG)     // 9
#define WOUT   (OSEG * SEG)      // 2048
#define BOUT   (WARPS * WOUT)    // 16384
#define HALO   (HSEG * SEG)      // 256
#define FIXN   256
#define MAXB   2048

__device__ double   g_psum[MAXB];
__device__ double   g_psumsq[MAXB];
__device__ unsigned g_ticket = 0;

__device__ __forceinline__ float fsqrt_ap(float x) {
    float y; asm("sqrt.approx.f32 %0, %1;" : "=f"(y) : "f"(x)); return y;
}

__global__ void __launch_bounds__(TPB, 6)
garch_fused(const float* __restrict__ r,
            const float* __restrict__ omega_p,
            const float* __restrict__ alpha_p,
            const float* __restrict__ beta_p,
            float* __restrict__ out,
            int n, int ntiles, int write_h)
{
    __shared__ float    swsum[WARPS], swq[WARPS];
    __shared__ unsigned s_ticket;
    __shared__ float    sh0;
    __shared__ double   red[TPB], red2[TPB];

    const int tid  = threadIdx.x;
    const int wid  = tid >> 5;
    const int lane = tid & 31;
    const unsigned FULL = 0xFFFFFFFFu;

    const float omega = *omega_p;
    const float alpha = *alpha_p;
    const float beta  = *beta_p;

    const float b2 = beta * beta, b4 = b2 * b2;
    const float M0 = b4 * b4;          // beta^8
    const float M1 = M0 * M0;          // beta^16
    const float M2 = M1 * M1;          // beta^32
    const float M3 = M2 * M2;          // beta^64
    const float M4 = M3 * M3;          // beta^128

    // lanepow = beta^(8*lane)
    float lanepow = 1.0f;
    { float p = M0; int e = lane;
      while (e) { if (e & 1) lanepow *= p; p *= p; e >>= 1; } }

    float vs = 0.0f, vq = 0.0f;

    for (int bb = blockIdx.x; bb < ntiles; bb += gridDim.x) {
        const int W0 = (bb * WARPS + wid) * WOUT;
        float c_prev = 0.0f;
        float wprev  = 0.0f;

        float4 A0, A1, B0, B1;
        {   // prefetch segment 0 (possibly left edge)
            int tb = W0 - HALO;
            int tl = tb + EPL * lane;
            if (tb >= 0 && tb + SEG <= n) {
                A0 = __ldcs((const float4*)(r + tl));
                A1 = __ldcs((const float4*)(r + tl + 4));
            } else {
                float* p0 = (float*)&A0; float* p1 = (float*)&A1;
                #pragma unroll
                for (int e = 0; e < 4; ++e) {
                    p0[e] = (tl + e     >= 0 && tl + e     < n) ? r[tl + e]     : 0.0f;
                    p1[e] = (tl + 4 + e >= 0 && tl + 4 + e < n) ? r[tl + 4 + e] : 0.0f;
                }
            }
        }

        #pragma unroll
        for (int s = 0; s < TSEG; ++s) {
            const int  t_base  = W0 - HALO + s * SEG;
            const int  tl      = t_base + EPL * lane;
            const bool is_out  = (s >= HSEG);
            const bool fastseg = (t_base >= 0) && (t_base + SEG <= n);

            if (s + 1 < TSEG) {        // prefetch next segment
                int tb2 = t_base + SEG;
                int tl2 = tb2 + EPL * lane;
                if (tb2 >= 0 && tb2 + SEG <= n) {
                    B0 = __ldcs((const float4*)(r + tl2));
                    B1 = __ldcs((const float4*)(r + tl2 + 4));
                } else {
                    float* p0 = (float*)&B0; float* p1 = (float*)&B1;
                    #pragma unroll
                    for (int e = 0; e < 4; ++e) {
                        p0[e] = (tl2 + e     >= 0 && tl2 + e     < n) ? r[tl2 + e]     : 0.0f;
                        p1[e] = (tl2 + 4 + e >= 0 && tl2 + 4 + e < n) ? r[tl2 + 4 + e] : 0.0f;
                    }
                }
            }

            float x0 = A0.x, x1 = A0.y, x2 = A0.z, x3 = A0.w;
            float x4 = A1.x, x5 = A1.y, x6 = A1.z, x7 = A1.w;

            // boundary shift: driver of element t is r[t-1]
            float pw   = __shfl_up_sync(FULL, x7, 1);
            float prev = (lane == 0) ? wprev : pw;
            wprev = __shfl_sync(FULL, x7, 31);

            // squares (variance + drivers share them)
            float q0 = x0 * x0, q1 = x1 * x1, q2 = x2 * x2, q3 = x3 * x3;
            float q4 = x4 * x4, q5 = x5 * x5, q6 = x6 * x6, q7 = x7 * x7;
            if (is_out && fastseg) {
                vs += ((x0 + x1) + (x2 + x3)) + ((x4 + x5) + (x6 + x7));
                vq += ((q0 + q1) + (q2 + q3)) + ((q4 + q5) + (q6 + q7));
            }

            float d0 = fmaf(alpha, prev * prev, omega);
            float d1 = fmaf(alpha, q0, omega);
            float d2 = fmaf(alpha, q1, omega);
            float d3 = fmaf(alpha, q2, omega);
            float d4 = fmaf(alpha, q3, omega);
            float d5 = fmaf(alpha, q4, omega);
            float d6 = fmaf(alpha, q5, omega);
            float d7 = fmaf(alpha, q6, omega);

            if (!fastseg) {            // cold: zero invalid drivers, add variance
                if (!(tl + 0 >= 1 && tl + 0 < n)) d0 = 0.0f;
                if (!(tl + 1 >= 1 && tl + 1 < n)) d1 = 0.0f;
                if (!(tl + 2 >= 1 && tl + 2 < n)) d2 = 0.0f;
                if (!(tl + 3 >= 1 && tl + 3 < n)) d3 = 0.0f;
                if (!(tl + 4 >= 1 && tl + 4 < n)) d4 = 0.0f;
                if (!(tl + 5 >= 1 && tl + 5 < n)) d5 = 0.0f;
                if (!(tl + 6 >= 1 && tl + 6 < n)) d6 = 0.0f;
                if (!(tl + 7 >= 1 && tl + 7 < n)) d7 = 0.0f;
                if (is_out) {
                    float xv[8] = {x0, x1, x2, x3, x4, x5, x6, x7};
                    #pragma unroll
                    for (int e = 0; e < 8; ++e)
                        if (tl + e >= 0 && tl + e < n) {
                            vs += xv[e]; vq = fmaf(xv[e], xv[e], vq);
                        }
                }
            } else if (t_base == 0 && lane == 0) {
                d0 = 0.0f;             // t=0: h_hat[0] = 0
            }

            // local chain end p7 (zero start)
            float c = d0;
            c = fmaf(beta, c, d1); c = fmaf(beta, c, d2);
            c = fmaf(beta, c, d3); c = fmaf(beta, c, d4);
            c = fmaf(beta, c, d5); c = fmaf(beta, c, d6);
            c = fmaf(beta, c, d7);

            // Kogge-Stone: S_l = E_l + beta^8 * S_{l-1}
            float S = c, t1;
            t1 = __shfl_up_sync(FULL, S, 1);  S = fmaf(M0, (lane >= 1)  ? t1 : 0.0f, S);
            t1 = __shfl_up_sync(FULL, S, 2);  S = fmaf(M1, (lane >= 2)  ? t1 : 0.0f, S);
            t1 = __shfl_up_sync(FULL, S, 4);  S = fmaf(M2, (lane >= 4)  ? t1 : 0.0f, S);
            t1 = __shfl_up_sync(FULL, S, 8);  S = fmaf(M3, (lane >= 8)  ? t1 : 0.0f, S);
            t1 = __shfl_up_sync(FULL, S, 16); S = fmaf(M4, (lane >= 16) ? t1 : 0.0f, S);

            float c_next = __shfl_sync(FULL, S, 31);   // beta^256*c_prev dropped
            float Sp     = __shfl_up_sync(FULL, S, 1);

            if (is_out) {
                float G = fmaf(lanepow, c_prev, (lane >= 1) ? Sp : 0.0f);
                // h chain from G (exact same recurrence)
                float h0 = fmaf(beta, G,  d0);
                float h1 = fmaf(beta, h0, d1);
                float h2 = fmaf(beta, h1, d2);
                float h3 = fmaf(beta, h2, d3);
                float h4 = fmaf(beta, h3, d4);
                float h5 = fmaf(beta, h4, d5);
                float h6 = fmaf(beta, h5, d6);
                float h7 = fmaf(beta, h6, d7);

                if (fastseg) {
                    float4 o0 = make_float4(fsqrt_ap(h0), fsqrt_ap(h1),
                                            fsqrt_ap(h2), fsqrt_ap(h3));
                    float4 o1 = make_float4(fsqrt_ap(h4), fsqrt_ap(h5),
                                            fsqrt_ap(h6), fsqrt_ap(h7));
                    __stcs((float4*)(out + tl),     o0);
                    __stcs((float4*)(out + tl + 4), o1);
                    if (write_h) {
                        __stcs((float4*)(out + n + tl),     make_float4(h0, h1, h2, h3));
                        __stcs((float4*)(out + n + tl + 4), make_float4(h4, h5, h6, h7));
                    }
                } else {
                    float hv[8] = {h0, h1, h2, h3, h4, h5, h6, h7};
                    #pragma unroll
                    for (int e = 0; e < 8; ++e) {
                        int t = tl + e;
                        if (t >= 0 && t < n) {
                            out[t] = fsqrt_ap(hv[e]);
                            if (write_h) out[n + t] = hv[e];
                        }
                    }
                }
            }
            c_prev = c_next;
            A0 = B0; A1 = B1;
        }
    }

    // ---- per-block deterministic variance partial ----
    #pragma unroll
    for (int off = 16; off; off >>= 1) {
        vs += __shfl_down_sync(FULL, vs, off);
        vq += __shfl_down_sync(FULL, vq, off);
    }
    if (lane == 0) { swsum[wid] = vs; swq[wid] = vq; }
    __syncthreads();
    if (tid == 0) {
        double a = 0.0, q = 0.0;
        #pragma unroll
        for (int w = 0; w < WARPS; ++w) { a += (double)swsum[w]; q += (double)swq[w]; }
        g_psum[blockIdx.x]   = a;
        g_psumsq[blockIdx.x] = q;
    }
    __syncthreads();

    // ---- ticket: last block reduces partials and patches the h0 term ----
    __threadfence();
    if (tid == 0) s_ticket = atomicAdd(&g_ticket, 1u);
    __syncthreads();
    if (s_ticket != (unsigned)(gridDim.x - 1)) return;

    if (tid == 0) g_ticket = 0;                  // reset for graph replays
    __threadfence();

    {
        double a = 0.0, q = 0.0;
        for (int i = tid; i < (int)gridDim.x; i += TPB) { a += g_psum[i]; q += g_psumsq[i]; }
        red[tid] = a; red2[tid] = q;
    }
    __syncthreads();
    for (int s = TPB / 2; s; s >>= 1) {
        if (tid < s) { red[tid] += red[tid + s]; red2[tid] += red2[tid + s]; }
        __syncthreads();
    }
    if (tid == 0) {
        double Ssum = red[0], Q = red2[0];
        sh0 = (float)((Q - Ssum * Ssum / (double)n) / (double)(n - 1));
    }
    __syncthreads();

    const float h0v = sh0;
    const int   lim = (FIXN < n) ? FIXN : n;
    if (write_h) {
        for (int t = tid; t < lim; t += TPB) {
            float pw2 = 1.0f, bb2 = beta; int e = t;
            while (e) { if (e & 1) pw2 *= bb2; bb2 *= bb2; e >>= 1; }
            float hh = (t == 0) ? h0v : fmaf(pw2, h0v, out[n + t]);
            out[n + t] = hh;
            out[t] = fsqrt_ap(hh);
        }
    } else {
        if (tid == 0) {
            float h = h0v;
            out[0] = fsqrt_ap(h);
            for (int t = 1; t < lim; ++t) {
                float rv = r[t - 1];
                h = fmaf(beta, h, fmaf(alpha * rv, rv, omega));
                out[t] = fsqrt_ap(h);
            }
        }
    }
}

extern "C" void kernel_launch(void* const* d_in, const int* in_sizes, int n_in,
                              void* d_out, int out_size)
{
    const float* r  = (const float*)d_in[0];
    const float* om = (const float*)d_in[1];
    const float* al = (const float*)d_in[2];
    const float* be = (const float*)d_in[3];
    float* out = (float*)d_out;

    const int n = in_sizes[0];
    const int write_h = (out_size >= 2 * n) ? 1 : 0;

    int ntiles = (n + BOUT - 1) / BOUT;
    if (ntiles < 1) ntiles = 1;
    int grid = (ntiles < MAXB) ? ntiles : MAXB;

    garch_fused<<<grid, TPB>>>(r, om, al, be, out, n, ntiles, write_h);
}